// round 17
// baseline (speedup 1.0000x reference)
#include <cuda_runtime.h>
#include <cuda_bf16.h>
#include <stdint.h>

#define NTOK 8192
#define DIM  1024
#define DK   128
#define DV   128

// ---------------- device globals (allocation-free scratch) ----------------
__device__ float g_v[NTOK * DV];
__device__ __align__(256) __nv_bfloat16 g_qkh[NTOK * DK];   // qk bf16 row-major
__device__ __align__(256) float g_ss[NTOK];                 // ||qk_i||^2 fp32
__device__ __align__(256) float g_O[NTOK * DV];             // numerators (atomic)
__device__ __align__(256) float g_l[NTOK];                  // denominators (atomic)
__device__ __align__(256) __nv_bfloat16 g_Wh[2][DK * DIM];  // W hi bf16 (0 qk, 1 v)
__device__ __align__(256) __nv_bfloat16 g_Wl[2][DK * DIM];  // W lo bf16

// ---------------- helpers ----------------
__device__ __forceinline__ uint32_t smem_to_u32(const void* p) {
    uint32_t a;
    asm("{ .reg .u64 t; cvta.to.shared.u64 t, %1; cvt.u32.u64 %0, t; }" : "=r"(a) : "l"(p));
    return a;
}
__device__ __forceinline__ void cp16(uint32_t dst, const void* src) {
    asm volatile("cp.async.cg.shared.global [%0], [%1], 16;" :: "r"(dst), "l"(src) : "memory");
}
#define CP_COMMIT() asm volatile("cp.async.commit_group;" ::: "memory")
#define CP_WAIT0()  asm volatile("cp.async.wait_group 0;" ::: "memory")

__device__ __forceinline__ uint32_t bf2_to_u32(__nv_bfloat162 v) {
    uint32_t u; *(__nv_bfloat162*)&u = v; return u;
}

#define LDSM_X4(r0, r1, r2, r3, a) \
    asm volatile("ldmatrix.sync.aligned.m8n8.x4.shared.b16 {%0,%1,%2,%3}, [%4];" \
                 : "=r"(r0), "=r"(r1), "=r"(r2), "=r"(r3) : "r"(a))
#define LDSM_X2_T(r0, r1, a) \
    asm volatile("ldmatrix.sync.aligned.m8n8.x2.trans.shared.b16 {%0,%1}, [%2];" \
                 : "=r"(r0), "=r"(r1) : "r"(a))
#define MMA16816(d, a, b0, b1) \
    asm volatile("mma.sync.aligned.m16n8k16.row.col.f32.bf16.bf16.f32 " \
                 "{%0,%1,%2,%3}, {%4,%5,%6,%7}, {%8,%9}, {%0,%1,%2,%3};" \
                 : "+f"((d)[0]), "+f"((d)[1]), "+f"((d)[2]), "+f"((d)[3]) \
                 : "r"((a)[0]), "r"((a)[1]), "r"((a)[2]), "r"((a)[3]), "r"(b0), "r"(b1))

// ============================================================================
// prep_w: Wqk/Wv fp32 -> global bf16 hi/lo (R12, proven)
// ============================================================================
__global__ __launch_bounds__(256, 4)
void prep_w_kernel(const float* __restrict__ Wqk, const float* __restrict__ Wv) {
    const int type = blockIdx.y;
    const float* W = type ? Wv : Wqk;
    __nv_bfloat16* dh = g_Wh[type];
    __nv_bfloat16* dl = g_Wl[type];
    const int base = (blockIdx.x * 256 + threadIdx.x) * 16;
#pragma unroll
    for (int j = 0; j < 4; j++) {
        float4 f = *(const float4*)&W[base + j * 4];
        __nv_bfloat162 h0 = __floats2bfloat162_rn(f.x, f.y);
        __nv_bfloat162 h1 = __floats2bfloat162_rn(f.z, f.w);
        __nv_bfloat162 l0 = __floats2bfloat162_rn(f.x - __bfloat162float(h0.x),
                                                  f.y - __bfloat162float(h0.y));
        __nv_bfloat162 l1 = __floats2bfloat162_rn(f.z - __bfloat162float(h1.x),
                                                  f.w - __bfloat162float(h1.y));
        uint2 uh; uh.x = bf2_to_u32(h0); uh.y = bf2_to_u32(h1);
        uint2 ul; ul.x = bf2_to_u32(l0); ul.y = bf2_to_u32(l1);
        *(uint2*)&dh[base + j * 4] = uh;
        *(uint2*)&dl[base + j * 4] = ul;
    }
}

// ============================================================================
// proj fused (HMMA): 64-row CTAs compute BOTH qk (2-product) and v (3-product).
// grid 128, 512 threads; warp = 16 rows (g = wid&3) x 64 output cols (cg = wid>>2).
// R17 fix: B tiles DOUBLE-BUFFERED (R16 raced cp.async writes vs MMA reads).
// smem: AH 9216 | AL 9216 | B[2] (hi+lo) 2x73728 | x-stage 16384 | ssred 512
// ============================================================================
#define PJ_ROWB 144
#define PJ_AH 0
#define PJ_AL 9216
#define PJ_BB(b) (18432 + (b) * 73728)   // hi at +0, lo at +36864
#define PJ_SA 165888
#define PJ_SSR 182272
#define PJ_SMEM 182784

__global__ __launch_bounds__(512, 1)
void proj_hmma_kernel(const float* __restrict__ x,
                      const float* __restrict__ bqk, const float* __restrict__ bv) {
    extern __shared__ char smem[];
    const uint32_t sb = smem_to_u32(smem);
    float* ssred = (float*)(smem + PJ_SSR);
    const int tid = threadIdx.x, wid = tid >> 5, lane = tid & 31;
    const int g = wid & 3, cg = wid >> 2;
    const int row0 = blockIdx.x * 64;

    const int rA = ((lane >> 3) & 1) * 8 + (lane & 7);
    const int kA = (lane >> 4) & 1;
    const int rB = ((lane >> 4) & 1) * 8 + (lane & 7);
    const int kB = (lane >> 3) & 1;
    const int qr = lane >> 2, c2 = lane & 3;
    const bool is_v = (cg >= 2);

    // zero g_O / g_l slices for attn's atomics
#pragma unroll
    for (int it = 0; it < 4; it++)
        ((float4*)g_O)[blockIdx.x * 2048 + it * 512 + tid] = make_float4(0.f, 0.f, 0.f, 0.f);
    if (tid < 64) g_l[blockIdx.x * 64 + tid] = 0.f;

    float acc[8][4];
#pragma unroll
    for (int f = 0; f < 8; f++)
#pragma unroll
        for (int q = 0; q < 4; q++) acc[f][q] = 0.f;

    // load helpers
    auto load_x = [&](int kk) {
#pragma unroll
        for (int it = 0; it < 2; it++) {
            int idx = it * 512 + tid;
            int r = idx >> 4, q = idx & 15;
            cp16(sb + PJ_SA + r * 256 + q * 16, &x[(size_t)(row0 + r) * DIM + kk + q * 4]);
        }
    };
    auto load_B = [&](int kk, int b) {
#pragma unroll
        for (int it = 0; it < 8; it++) {
            int idx = it * 512 + tid;
            int wr = idx >> 4, sel = (idx >> 3) & 1, cc = idx & 7;
            const __nv_bfloat16* src = sel ? g_Wl[wr >> 7] : g_Wh[wr >> 7];
            cp16(sb + PJ_BB(b) + sel * 36864 + wr * PJ_ROWB + cc * 16,
                 &src[(size_t)(wr & 127) * DIM + kk + cc * 8]);
        }
    };

    // preload chunk 0
    load_x(0);
    load_B(0, 0);
    CP_COMMIT();

    for (int c = 0; c < 16; c++) {
        const int cb = c & 1;
        CP_WAIT0();
        __syncthreads();   // chunk-c data arrived; prior MMAs done with B[cb]

        // convert x staging -> A hi/lo
#pragma unroll
        for (int it = 0; it < 2; it++) {
            int idx = it * 512 + tid;
            int r = idx >> 4, kq = (idx & 15) * 4;
            float4 fa = *(const float4*)(smem + PJ_SA + r * 256 + kq * 4);
            __nv_bfloat162 h0 = __floats2bfloat162_rn(fa.x, fa.y);
            __nv_bfloat162 h1 = __floats2bfloat162_rn(fa.z, fa.w);
            __nv_bfloat162 l0 = __floats2bfloat162_rn(fa.x - __bfloat162float(h0.x),
                                                      fa.y - __bfloat162float(h0.y));
            __nv_bfloat162 l1 = __floats2bfloat162_rn(fa.z - __bfloat162float(h1.x),
                                                      fa.w - __bfloat162float(h1.y));
            uint2 u;
            u.x = bf2_to_u32(h0); u.y = bf2_to_u32(h1);
            *(uint2*)(smem + PJ_AH + r * PJ_ROWB + kq * 2) = u;
            u.x = bf2_to_u32(l0); u.y = bf2_to_u32(l1);
            *(uint2*)(smem + PJ_AL + r * PJ_ROWB + kq * 2) = u;
        }
        __syncthreads();   // A ready; x-staging reads done

        // prefetch chunk c+1 (x -> staging, B -> OTHER buffer)
        if (c + 1 < 16) {
            const int kk = (c + 1) * 64;
            load_x(kk);
            load_B(kk, cb ^ 1);
            CP_COMMIT();
        }

        // A frags (al only for v warps)
        uint32_t ah[4][4], al[4][4];
        const uint32_t arh = sb + PJ_AH + (uint32_t)(g * 16 + rA) * PJ_ROWB;
        const uint32_t arl = sb + PJ_AL + (uint32_t)(g * 16 + rA) * PJ_ROWB;
#pragma unroll
        for (int s = 0; s < 4; s++) {
            LDSM_X4(ah[s][0], ah[s][1], ah[s][2], ah[s][3], arh + (s * 16 + kA * 8) * 2);
            if (is_v)
                LDSM_X4(al[s][0], al[s][1], al[s][2], al[s][3], arl + (s * 16 + kA * 8) * 2);
        }

        // MMAs from B[cb]
        const uint32_t bh_base = sb + PJ_BB(cb);
#pragma unroll
        for (int s = 0; s < 4; s++) {
#pragma unroll
            for (int ng = 0; ng < 4; ng++) {
                uint32_t bh0, bh1, bh2, bh3, bl0, bl1, bl2, bl3;
                const uint32_t boff = (uint32_t)(cg * 64 + ng * 16 + rB) * PJ_ROWB
                                      + (s * 16 + kB * 8) * 2;
                LDSM_X4(bh0, bh1, bh2, bh3, bh_base + boff);
                LDSM_X4(bl0, bl1, bl2, bl3, bh_base + 36864 + boff);
                MMA16816(acc[2 * ng],     ah[s], bh0, bh1);
                MMA16816(acc[2 * ng + 1], ah[s], bh2, bh3);
                MMA16816(acc[2 * ng],     ah[s], bl0, bl1);
                MMA16816(acc[2 * ng + 1], ah[s], bl2, bl3);
                if (is_v) {
                    MMA16816(acc[2 * ng],     al[s], bh0, bh1);
                    MMA16816(acc[2 * ng + 1], al[s], bh2, bh3);
                }
            }
        }
    }

    // epilogue
    const int rl = row0 + g * 16 + qr;
    const int rh = rl + 8;
    if (!is_v) {
        float ss0 = 0.f, ss1 = 0.f;
#pragma unroll
        for (int ng = 0; ng < 4; ng++)
#pragma unroll
            for (int j = 0; j < 2; j++) {
                const int f = 2 * ng + j;
                const int col = cg * 64 + ng * 16 + 8 * j + 2 * c2;
                float2 bb = *(const float2*)&bqk[col];
                float c0 = acc[f][0] + bb.x, c1 = acc[f][1] + bb.y;
                float c2v = acc[f][2] + bb.x, c3 = acc[f][3] + bb.y;
                ss0 += c0 * c0 + c1 * c1;
                ss1 += c2v * c2v + c3 * c3;
                *(uint32_t*)&g_qkh[(size_t)rl * DK + col] = bf2_to_u32(__floats2bfloat162_rn(c0, c1));
                *(uint32_t*)&g_qkh[(size_t)rh * DK + col] = bf2_to_u32(__floats2bfloat162_rn(c2v, c3));
            }
        ss0 += __shfl_xor_sync(0xffffffffu, ss0, 1);
        ss0 += __shfl_xor_sync(0xffffffffu, ss0, 2);
        ss1 += __shfl_xor_sync(0xffffffffu, ss1, 1);
        ss1 += __shfl_xor_sync(0xffffffffu, ss1, 2);
        if (c2 == 0) {
            ssred[cg * 64 + g * 16 + qr]     = ss0;
            ssred[cg * 64 + g * 16 + qr + 8] = ss1;
        }
    } else {
#pragma unroll
        for (int ng = 0; ng < 4; ng++)
#pragma unroll
            for (int j = 0; j < 2; j++) {
                const int f = 2 * ng + j;
                const int vcol = (cg - 2) * 64 + ng * 16 + 8 * j + 2 * c2;
                float2 bb = *(const float2*)&bv[vcol];
                float2 v0; v0.x = acc[f][0] + bb.x; v0.y = acc[f][1] + bb.y;
                float2 v1; v1.x = acc[f][2] + bb.x; v1.y = acc[f][3] + bb.y;
                *(float2*)&g_v[(size_t)rl * DV + vcol] = v0;
                *(float2*)&g_v[(size_t)rh * DV + vcol] = v1;
            }
    }
    __syncthreads();
    if (tid < 64) g_ss[row0 + tid] = ssred[tid] + ssred[64 + tid];
}

// ============================================================================
// attn_sym: one CTA per unordered pair — R15 champion, verbatim
// ============================================================================
#define ROWB 272
#define SB0 0
#define SB1 34816
#define SB2 69632
#define SM_THRJ 104448
#define SM_MJ   104960
#define SM_SLB  105472
#define ATT_SMEM 105984

__global__ __launch_bounds__(256, 2)
void attn_kernel() {
    const int bi = blockIdx.x, bj = blockIdx.y;
    if (bj < bi) return;
    const int diag = (bi == bj);
    const int gI = bi * 128, gJ = bj * 128;

    extern __shared__ char smem[];
    const uint32_t sb = smem_to_u32(smem);
    float* thrJ = (float*)(smem + SM_THRJ);
    float* mJ   = (float*)(smem + SM_MJ);
    float* slB  = (float*)(smem + SM_SLB);
    const int tid = threadIdx.x, wid = tid >> 5, lane = tid & 31;

    const int rA = ((lane >> 3) & 1) * 8 + (lane & 7);
    const int kA = (lane >> 4) & 1;
    const int rB = ((lane >> 4) & 1) * 8 + (lane & 7);
    const int kB = (lane >> 3) & 1;
    const int qr = lane >> 2, c2 = lane & 3;

    const int rlL = wid * 16 + qr, rhL = rlL + 8;
    const float m0 = g_ss[gI + rlL], m1 = g_ss[gI + rhL];
    const float thr0 = m0 - 14.f, thr1 = m1 - 14.f;

#pragma unroll
    for (int it = 0; it < 8; it++) {
        int c = it * 256 + tid;
        int r = c >> 4, cc = (c & 15) * 8;
        cp16(sb + SB0 + r * ROWB + cc * 2, &g_qkh[(size_t)(gI + r) * DK + cc]);
        cp16(sb + SB1 + r * ROWB + cc * 2, &g_qkh[(size_t)(gJ + r) * DK + cc]);
    }
    if (tid < 128) {
        float s = g_ss[gJ + tid];
        thrJ[tid] = s - 14.f;
        mJ[tid] = s;
        slB[tid] = 0.f;
    }
    CP_COMMIT(); CP_WAIT0();
    __syncthreads();

    uint32_t qa[8][4];
    {
        const uint32_t qrow = sb + SB0 + (uint32_t)(wid * 16 + rA) * ROWB;
#pragma unroll
        for (int s = 0; s < 8; s++)
            LDSM_X4(qa[s][0], qa[s][1], qa[s][2], qa[s][3], qrow + (s * 16 + kA * 8) * 2);
    }

    float sa[16][4];
#pragma unroll
    for (int nt = 0; nt < 16; nt++)
#pragma unroll
        for (int q = 0; q < 4; q++) sa[nt][q] = 0.f;
#pragma unroll
    for (int s = 0; s < 8; s++) {
        const uint32_t kcol = sb + SB1 + (uint32_t)((s * 16 + kB * 8) * 2);
#pragma unroll
        for (int np = 0; np < 8; np++) {
            uint32_t b0, b1, b2, b3;
            LDSM_X4(b0, b1, b2, b3, kcol + (uint32_t)(np * 16 + rB) * ROWB);
            MMA16816(sa[2 * np],     qa[s], b0, b1);
            MMA16816(sa[2 * np + 1], qa[s], b2, b3);
        }
    }

    float mx0 = -3.0e38f, mx1 = -3.0e38f;
#pragma unroll
    for (int nt = 0; nt < 16; nt++) {
        mx0 = fmaxf(mx0, fmaxf(sa[nt][0], sa[nt][1]));
        mx1 = fmaxf(mx1, fmaxf(sa[nt][2], sa[nt][3]));
    }
    int pred = ((mx0 >= thr0) || (mx1 >= thr1)) ? 1 : 0;
    if (!diag) {
        int pb = 0;
#pragma unroll
        for (int nt = 0; nt < 16; nt++) {
            const int col = nt * 8 + 2 * c2;
            float2 tj = *(const float2*)&thrJ[col];
            pb |= (sa[nt][0] >= tj.x) | (sa[nt][1] >= tj.y) |
                  (sa[nt][2] >= tj.x) | (sa[nt][3] >= tj.y);
        }
        if (pb) pred |= 2;
    }
    const int act = __syncthreads_or(pred);
    if (!act) return;

    if (act & 2) {
#pragma unroll
        for (int nt = 0; nt < 16; nt++) {
            const int col = nt * 8 + 2 * c2;
            float2 mj2 = *(const float2*)&mJ[col];
            __nv_bfloat16 b00 = __float2bfloat16_rn(__expf(sa[nt][0] - mj2.x));
            __nv_bfloat16 b01 = __float2bfloat16_rn(__expf(sa[nt][1] - mj2.y));
            __nv_bfloat16 b10 = __float2bfloat16_rn(__expf(sa[nt][2] - mj2.x));
            __nv_bfloat16 b11 = __float2bfloat16_rn(__expf(sa[nt][3] - mj2.y));
            *(__nv_bfloat16*)(smem + SB0 + col * ROWB + rlL * 2) = b00;
            *(__nv_bfloat16*)(smem + SB0 + (col + 1) * ROWB + rlL * 2) = b01;
            *(__nv_bfloat16*)(smem + SB0 + col * ROWB + rhL * 2) = b10;
            *(__nv_bfloat16*)(smem + SB0 + (col + 1) * ROWB + rhL * 2) = b11;
            atomicAdd(&slB[col],     __bfloat162float(b00) + __bfloat162float(b10));
            atomicAdd(&slB[col + 1], __bfloat162float(b01) + __bfloat162float(b11));
        }
    }

    if (act & 1) {
#pragma unroll
        for (int it = 0; it < 16; it++) {
            int idx = it * 256 + tid;
            int r = idx >> 5, cq = (idx & 31) * 4;
            float4 f = *(const float4*)&g_v[(size_t)(gJ + r) * DV + cq];
            __nv_bfloat162 h0 = __floats2bfloat162_rn(f.x, f.y);
            __nv_bfloat162 h1 = __floats2bfloat162_rn(f.z, f.w);
            __nv_bfloat162 e0 = __floats2bfloat162_rn(f.x - __bfloat162float(h0.x),
                                                      f.y - __bfloat162float(h0.y));
            __nv_bfloat162 e1 = __floats2bfloat162_rn(f.z - __bfloat162float(h1.x),
                                                      f.w - __bfloat162float(h1.y));
            uint2 uh; uh.x = bf2_to_u32(h0); uh.y = bf2_to_u32(h1);
            uint2 ul; ul.x = bf2_to_u32(e0); ul.y = bf2_to_u32(e1);
            *(uint2*)(smem + SB1 + r * ROWB + cq * 2) = uh;
            *(uint2*)(smem + SB2 + r * ROWB + cq * 2) = ul;
        }
        __syncthreads();

        float oa[16][4];
#pragma unroll
        for (int nt = 0; nt < 16; nt++)
#pragma unroll
            for (int q = 0; q < 4; q++) oa[nt][q] = 0.f;
        float l0 = 0.f, l1 = 0.f;

#pragma unroll
        for (int s = 0; s < 8; s++) {
            uint32_t pa[4];
            __nv_bfloat162 b;
            b = __floats2bfloat162_rn(__expf(sa[2 * s][0] - m0), __expf(sa[2 * s][1] - m0));
            pa[0] = bf2_to_u32(b); l0 += __bfloat162float(b.x) + __bfloat162float(b.y);
            b = __floats2bfloat162_rn(__expf(sa[2 * s][2] - m1), __expf(sa[2 * s][3] - m1));
            pa[1] = bf2_to_u32(b); l1 += __bfloat162float(b.x) + __bfloat162float(b.y);
            b = __floats2bfloat162_rn(__expf(sa[2 * s + 1][0] - m0), __expf(sa[2 * s + 1][1] - m0));
            pa[2] = bf2_to_u32(b); l0 += __bfloat162float(b.x) + __bfloat162float(b.y);
            b = __floats2bfloat162_rn(__expf(sa[2 * s + 1][2] - m1), __expf(sa[2 * s + 1][3] - m1));
            pa[3] = bf2_to_u32(b); l1 += __bfloat162float(b.x) + __bfloat162float(b.y);

            const uint32_t vrow = (uint32_t)(s * 16 + rA) * ROWB;
#pragma unroll
            for (int nt = 0; nt < 16; nt++) {
                uint32_t bh0, bh1;
                LDSM_X2_T(bh0, bh1, sb + SB1 + vrow + nt * 16);
                MMA16816(oa[nt], pa, bh0, bh1);
            }
#pragma unroll
            for (int nt = 0; nt < 16; nt++) {
                uint32_t bl0, bl1;
                LDSM_X2_T(bl0, bl1, sb + SB2 + vrow + nt * 16);
                MMA16816(oa[nt], pa, bl0, bl1);
            }
        }
#pragma unroll
        for (int nt = 0; nt < 16; nt++) {
            const int col = nt * 8 + 2 * c2;
            atomicAdd(&g_O[(size_t)(gI + rlL) * DV + col],     oa[nt][0]);
            atomicAdd(&g_O[(size_t)(gI + rlL) * DV + col + 1], oa[nt][1]);
            atomicAdd(&g_O[(size_t)(gI + rhL) * DV + col],     oa[nt][2]);
            atomicAdd(&g_O[(size_t)(gI + rhL) * DV + col + 1], oa[nt][3]);
        }
        l0 += __shfl_xor_sync(0xffffffffu, l0, 1);
        l0 += __shfl_xor_sync(0xffffffffu, l0, 2);
        l1 += __shfl_xor_sync(0xffffffffu, l1, 1);
        l1 += __shfl_xor_sync(0xffffffffu, l1, 2);
        if (c2 == 0) {
            atomicAdd(&g_l[gI + rlL], l0);
            atomicAdd(&g_l[gI + rhL], l1);
        }
    }

    if (act & 2) {
        __syncthreads();
#pragma unroll
        for (int it = 0; it < 16; it++) {
            int idx = it * 256 + tid;
            int r = idx >> 5, cq = (idx & 31) * 4;
            float4 f = *(const float4*)&g_v[(size_t)(gI + r) * DV + cq];
            __nv_bfloat162 h0 = __floats2bfloat162_rn(f.x, f.y);
            __nv_bfloat162 h1 = __floats2bfloat162_rn(f.z, f.w);
            __nv_bfloat162 e0 = __floats2bfloat162_rn(f.x - __bfloat162float(h0.x),
                                                      f.y - __bfloat162float(h0.y));
            __nv_bfloat162 e1 = __floats2bfloat162_rn(f.z - __bfloat162float(h1.x),
                                                      f.w - __bfloat162float(h1.y));
            uint2 uh; uh.x = bf2_to_u32(h0); uh.y = bf2_to_u32(h1);
            uint2 ul; ul.x = bf2_to_u32(e0); ul.y = bf2_to_u32(e1);
            *(uint2*)(smem + SB1 + r * ROWB + cq * 2) = uh;
            *(uint2*)(smem + SB2 + r * ROWB + cq * 2) = ul;
        }
        __syncthreads();

        float oa[16][4];
#pragma unroll
        for (int nt = 0; nt < 16; nt++)
#pragma unroll
            for (int q = 0; q < 4; q++) oa[nt][q] = 0.f;

        const uint32_t prow = sb + SB0 + (uint32_t)(wid * 16 + rA) * ROWB;
#pragma unroll
        for (int s = 0; s < 8; s++) {
            uint32_t pa[4];
            LDSM_X4(pa[0], pa[1], pa[2], pa[3], prow + (s * 16 + kA * 8) * 2);
            const uint32_t vrow = (uint32_t)(s * 16 + rA) * ROWB;
#pragma unroll
            for (int nt = 0; nt < 16; nt++) {
                uint32_t bh0, bh1;
                LDSM_X2_T(bh0, bh1, sb + SB1 + vrow + nt * 16);
                MMA16816(oa[nt], pa, bh0, bh1);
            }
#pragma unroll
            for (int nt = 0; nt < 16; nt++) {
                uint32_t bl0, bl1;
                LDSM_X2_T(bl0, bl1, sb + SB2 + vrow + nt * 16);
                MMA16816(oa[nt], pa, bl0, bl1);
            }
        }
#pragma unroll
        for (int nt = 0; nt < 16; nt++) {
            const int col = nt * 8 + 2 * c2;
            atomicAdd(&g_O[(size_t)(gJ + rlL) * DV + col],     oa[nt][0]);
            atomicAdd(&g_O[(size_t)(gJ + rlL) * DV + col + 1], oa[nt][1]);
            atomicAdd(&g_O[(size_t)(gJ + rhL) * DV + col],     oa[nt][2]);
            atomicAdd(&g_O[(size_t)(gJ + rhL) * DV + col + 1], oa[nt][3]);
        }
        if (tid < 128) atomicAdd(&g_l[gJ + tid], slB[tid]);
    }
}

// ============================================================================
// combine: out = O / l  (grid 512, 2 f4/thread)
// ============================================================================
__global__ __launch_bounds__(256, 4)
void combine_kernel(float* __restrict__ out) {
    const int base = blockIdx.x * 256 + threadIdx.x;
#pragma unroll
    for (int j = 0; j < 2; j++) {
        const int i4 = base + j * 131072;
        const float inv = 1.0f / g_l[i4 >> 5];
        float4 a = ((const float4*)g_O)[i4];
        float4 o = make_float4(a.x * inv, a.y * inv, a.z * inv, a.w * inv);
        ((float4*)out)[i4] = o;
    }
}

// ---------------------------------------------------------------------------
extern "C" void kernel_launch(void* const* d_in, const int* in_sizes, int n_in,
                              void* d_out, int out_size) {
    const float* x   = (const float*)d_in[0];
    const float* Wqk = (const float*)d_in[1];
    const float* bqk = (const float*)d_in[2];
    const float* Wv  = (const float*)d_in[3];
    const float* bv  = (const float*)d_in[4];
    float* out = (float*)d_out;

    cudaFuncSetAttribute(proj_hmma_kernel, cudaFuncAttributeMaxDynamicSharedMemorySize, PJ_SMEM);
    cudaFuncSetAttribute(attn_kernel, cudaFuncAttributeMaxDynamicSharedMemorySize, ATT_SMEM);

    prep_w_kernel<<<dim3(32, 2), 256>>>(Wqk, Wv);
    proj_hmma_kernel<<<128, 512, PJ_SMEM>>>(x, bqk, bv);
    attn_kernel<<<dim3(64, 64), 256, ATT_SMEM>>>();
    combine_kernel<<<512, 256>>>(out);
}